// round 5
// baseline (speedup 1.0000x reference)
#include <cuda_runtime.h>
#include <cuda_bf16.h>
#include <math.h>
#include <stdint.h>

#define N_MLP  16
#define LATENT 1024
#define S0     512
#define S1     256
#define S2     128
#define OUTD   3
#define TG     128
#define NTHR   512

// ---------------- SMEM layout (bytes) --------------------------------
// h1 q-tiles: q*32768 (hi 16K, lo 16K), q=0..3        0      .. 131072
// A buf aliases q3 tile (written only at nh1 epilogue)
// B double buffers                                    131072 .. 196608
// consts (b1f 256f | b2f 128f | w3f 384f)             196608 .. 199680
#define H1HI_OFF(q) ((q)*32768u)
#define H1LO_OFF(q) ((q)*32768u + 16384u)
#define AHI_OFF 98304u
#define ALO_OFF 114688u
#define BHI_OFF(b) (131072u + (b)*32768u)
#define BLO_OFF(b) (131072u + (b)*32768u + 16384u)
#define CONST_OFF 196608u
#define SMEM_TOTAL (CONST_OFF + 768u * 4u)

#define SWZ(x) ((x) ^ (((x) >> 3) & 0x70u))

// ---------------- device scratch -------------------------------------
__device__ __align__(16) __nv_bfloat16 g_W1hi[N_MLP * S1 * S0];
__device__ __align__(16) __nv_bfloat16 g_W1lo[N_MLP * S1 * S0];
__device__ __align__(16) __nv_bfloat16 g_W2hi[N_MLP * S2 * S1];
__device__ __align__(16) __nv_bfloat16 g_W2lo[N_MLP * S2 * S1];
__device__ __align__(16) float4 g_l0[N_MLP * S0];   // {c0, wx, wy, 0}

// ---------------- helpers --------------------------------------------
__device__ __forceinline__ uint32_t smem_u32(const void* p) {
    uint32_t a;
    asm("{ .reg .u64 t; cvta.to.shared.u64 t, %1; cvt.u32.u64 %0, t; }"
        : "=r"(a) : "l"(p));
    return a;
}
__device__ __forceinline__ void ldsm4(uint32_t* r, uint32_t addr) {
    asm volatile("ldmatrix.sync.aligned.m8n8.x4.shared.b16 {%0,%1,%2,%3}, [%4];"
                 : "=r"(r[0]), "=r"(r[1]), "=r"(r[2]), "=r"(r[3]) : "r"(addr));
}
__device__ __forceinline__ void mma_bf16(float* d, const uint32_t* a, const uint32_t* b) {
    asm volatile(
        "mma.sync.aligned.m16n8k16.row.col.f32.bf16.bf16.f32 "
        "{%0,%1,%2,%3}, {%4,%5,%6,%7}, {%8,%9}, {%0,%1,%2,%3};"
        : "+f"(d[0]), "+f"(d[1]), "+f"(d[2]), "+f"(d[3])
        : "r"(a[0]), "r"(a[1]), "r"(a[2]), "r"(a[3]), "r"(b[0]), "r"(b[1]));
}
__device__ __forceinline__ void split2(float a, float b, uint32_t& hi, uint32_t& lo) {
    __nv_bfloat16 ha = __float2bfloat16(a), hb = __float2bfloat16(b);
    float ra = a - __bfloat162float(ha);
    float rb = b - __bfloat162float(hb);
    __nv_bfloat16 la = __float2bfloat16(ra), lb = __float2bfloat16(rb);
    hi = ((uint32_t)__bfloat16_as_ushort(hb) << 16) | (uint32_t)__bfloat16_as_ushort(ha);
    lo = ((uint32_t)__bfloat16_as_ushort(lb) << 16) | (uint32_t)__bfloat16_as_ushort(la);
}
__device__ __forceinline__ void cpa16(uint32_t dst, const void* src) {
    asm volatile("cp.async.cg.shared.global [%0], [%1], 16;"
                 :: "r"(dst), "l"(src) : "memory");
}
#define CP_COMMIT() asm volatile("cp.async.commit_group;" ::: "memory")
#define CP_WAIT1()  asm volatile("cp.async.wait_group 1;" ::: "memory")
#define CP_WAIT0()  asm volatile("cp.async.wait_group 0;" ::: "memory")

// ---------------- prep kernels ---------------------------------------
__global__ void prep_c0(const float* __restrict__ x0,
                        const float* __restrict__ W0a,
                        const float* __restrict__ b0a,
                        const float* __restrict__ b0b,
                        const float* __restrict__ W0b) {
    int w    = (blockIdx.x * blockDim.x + threadIdx.x) >> 5;
    int lane = threadIdx.x & 31;
    if (w >= N_MLP * S0) return;
    const float* row = W0a + (size_t)w * LATENT;
    float s = 0.f;
    #pragma unroll 4
    for (int i = lane; i < LATENT; i += 32) s += row[i] * x0[i];
    #pragma unroll
    for (int off = 16; off; off >>= 1) s += __shfl_xor_sync(0xffffffffu, s, off);
    if (lane == 0)
        g_l0[w] = make_float4(s + b0a[w] + b0b[w], W0b[w * 2], W0b[w * 2 + 1], 0.f);
}

__global__ void prep_split(const float* __restrict__ W1,
                           const float* __restrict__ W2) {
    const int t1 = N_MLP * S1 * S0;
    for (int i = blockIdx.x * blockDim.x + threadIdx.x; i < t1;
         i += gridDim.x * blockDim.x) {
        float v = W1[i];
        __nv_bfloat16 h = __float2bfloat16(v);
        g_W1hi[i] = h;
        g_W1lo[i] = __float2bfloat16(v - __bfloat162float(h));
    }
    const int t2 = N_MLP * S2 * S1;
    for (int i = blockIdx.x * blockDim.x + threadIdx.x; i < t2;
         i += gridDim.x * blockDim.x) {
        float v = W2[i];
        __nv_bfloat16 h = __float2bfloat16(v);
        g_W2hi[i] = h;
        g_W2lo[i] = __float2bfloat16(v - __bfloat162float(h));
    }
}

// ---------------- main HMMA kernel ------------------------------------
__global__ __launch_bounds__(NTHR, 1)
void mlp_hmma(const float* __restrict__ b1,
              const float* __restrict__ b2,
              const float* __restrict__ W3,
              const float* __restrict__ b3,
              const int*   __restrict__ n_ptr,
              float*       __restrict__ out,
              int G) {
    extern __shared__ char smch[];
    const uint32_t smb = smem_u32(smch);
    float* b1f = (float*)(smch + CONST_OFF);
    float* b2f = b1f + 256;
    float* w3f = b1f + 384;

    const int m    = blockIdx.y;
    const int tile = blockIdx.x;
    const int tid  = threadIdx.x;
    const int w    = tid >> 5;
    const int lane = tid & 31;
    const int n    = *n_ptr;

    for (int i = tid; i < S1; i += NTHR) b1f[i] = b1[m * S1 + i];
    for (int i = tid; i < S2; i += NTHR) b2f[i] = b2[m * S2 + i];
    for (int i = tid; i < OUTD * S2; i += NTHR) w3f[i] = W3[(size_t)m * OUTD * S2 + i];

    // per-thread A-staging coords: row = tid>>2 (0..127), quarter = tid&3
    const int ar = tid >> 2, aq = tid & 3;
    float gxr, gyr;
    {
        int p = tile * TG + ar;
        int px = 0, py = 0;
        if (p < G) { px = p % n; py = p / n; }
        float step = 2.0f / (float)(n - 1);
        gxr = -1.0f + step * (float)px;
        gyr = -1.0f + step * (float)py;
    }
    const float4* l0 = g_l0 + m * S0;

    const int mw = w & 3, nw = w >> 2;
    const int m0 = mw * 32, n0 = nw * 32;
    const uint32_t a_row = (uint32_t)(lane & 15);
    const uint32_t a_col = (uint32_t)((lane >> 4) * 16);
    const uint32_t b_row = (uint32_t)((lane & 7) + ((lane & 16) >> 1));
    const uint32_t b_col = (uint32_t)(((lane >> 3) & 1) * 16);
    const int cl2 = (lane & 3) * 2;

    float C[2][4][4];

    // ---- A staging: h0 chunk kc (64 cols) -> A buf ----
    #define STAGE_A(kc) do {                                                   \
        char* ph = smch + AHI_OFF;                                             \
        char* pl = smch + ALO_OFF;                                             \
        _Pragma("unroll")                                                      \
        for (int i = 0; i < 4; ++i) {                                          \
            int col = aq * 16 + i * 4;                                         \
            int k   = (kc) * 64 + col;                                         \
            float4 p0 = l0[k], p1 = l0[k + 1], p2 = l0[k + 2], p3 = l0[k + 3]; \
            float v0 = fmaxf(fmaf(p0.y, gxr, fmaf(p0.z, gyr, p0.x)), 0.f);     \
            float v1 = fmaxf(fmaf(p1.y, gxr, fmaf(p1.z, gyr, p1.x)), 0.f);     \
            float v2 = fmaxf(fmaf(p2.y, gxr, fmaf(p2.z, gyr, p2.x)), 0.f);     \
            float v3 = fmaxf(fmaf(p3.y, gxr, fmaf(p3.z, gyr, p3.x)), 0.f);     \
            uint32_t h0u, lo0u, h1u, lo1u;                                     \
            split2(v0, v1, h0u, lo0u);                                         \
            split2(v2, v3, h1u, lo1u);                                         \
            uint32_t off = SWZ((uint32_t)(ar * 128 + col * 2));                \
            *(uint2*)(ph + off) = make_uint2(h0u, h1u);                        \
            *(uint2*)(pl + off) = make_uint2(lo0u, lo1u);                      \
        }                                                                      \
    } while (0)

    // ---- B prefetch for step s ----
    #define ISSUE_B(s) do {                                                    \
        int bb = (s) & 1;                                                      \
        const uint4 *sh, *sl; int strd;                                        \
        if ((s) < 16) {                                                        \
            int nh = (s) >> 3, kc = (s) & 7;                                   \
            sh = (const uint4*)g_W1hi + ((size_t)m * 256 + nh * 128) * 64 + kc * 8; \
            sl = (const uint4*)g_W1lo + ((size_t)m * 256 + nh * 128) * 64 + kc * 8; \
            strd = 64;                                                         \
        } else {                                                               \
            int kc = (s) - 16;                                                 \
            sh = (const uint4*)g_W2hi + (size_t)m * 128 * 32 + kc * 8;         \
            sl = (const uint4*)g_W2lo + (size_t)m * 128 * 32 + kc * 8;         \
            strd = 32;                                                         \
        }                                                                      \
        _Pragma("unroll")                                                      \
        for (int jj = 0; jj < 2; ++jj) {                                       \
            int idx = tid + jj * NTHR;                                         \
            int row = idx >> 3, c16 = idx & 7;                                 \
            uint32_t off = SWZ((uint32_t)(row * 128 + c16 * 16));              \
            cpa16(smb + BHI_OFF(bb) + off, sh + row * strd + c16);             \
            cpa16(smb + BLO_OFF(bb) + off, sl + row * strd + c16);             \
        }                                                                      \
        CP_COMMIT();                                                           \
    } while (0)

    __syncthreads();          // consts staged
    STAGE_A(0);
    ISSUE_B(0);
    ISSUE_B(1);

    // init C for layer1 nh=0
    #pragma unroll
    for (int mt = 0; mt < 2; ++mt)
        #pragma unroll
        for (int nt = 0; nt < 4; ++nt) {
            int c = n0 + nt * 8 + cl2;
            C[mt][nt][0] = b1f[c]; C[mt][nt][1] = b1f[c + 1];
            C[mt][nt][2] = b1f[c]; C[mt][nt][3] = b1f[c + 1];
        }

    for (int s = 0; s < 20; ++s) {
        const int b = s & 1;
        if (s == 19) { CP_WAIT0(); } else { CP_WAIT1(); }
        __syncthreads();

        uint32_t aHIb, aLOb;
        if (s < 16) { aHIb = smb + AHI_OFF; aLOb = smb + ALO_OFF; }
        else        { int q = s - 16; aHIb = smb + H1HI_OFF(q); aLOb = smb + H1LO_OFF(q); }
        const uint32_t bHIb = smb + BHI_OFF(b), bLOb = smb + BLO_OFF(b);

        #pragma unroll
        for (int k16 = 0; k16 < 4; ++k16) {
            const uint32_t kb2 = (uint32_t)(k16 * 32);
            uint32_t ahi[2][4], alo[2][4];
            #pragma unroll
            for (int mt = 0; mt < 2; ++mt) {
                uint32_t aoff = SWZ((uint32_t)((m0 + mt * 16 + a_row) * 128) + kb2 + a_col);
                ldsm4(ahi[mt], aHIb + aoff);
                ldsm4(alo[mt], aLOb + aoff);
            }
            #pragma unroll
            for (int nt2 = 0; nt2 < 2; ++nt2) {
                uint32_t boff = SWZ((uint32_t)((n0 + nt2 * 16 + b_row) * 128) + kb2 + b_col);
                uint32_t bh[4], bl[4];
                ldsm4(bh, bHIb + boff);
                ldsm4(bl, bLOb + boff);
                #pragma unroll
                for (int mt = 0; mt < 2; ++mt)
                    #pragma unroll
                    for (int s2 = 0; s2 < 2; ++s2) {
                        float* d = C[mt][nt2 * 2 + s2];
                        mma_bf16(d, ahi[mt], bh + 2 * s2);
                        mma_bf16(d, ahi[mt], bl + 2 * s2);
                        mma_bf16(d, alo[mt], bh + 2 * s2);
                    }
            }
        }
        __syncthreads();

        if (s + 2 < 20) ISSUE_B(s + 2);

        if (s == 7 || s == 15) {
            // h1 epilogue for nh = s>>3
            const int nh = s >> 3;
            #pragma unroll
            for (int mt = 0; mt < 2; ++mt) {
                int r = m0 + mt * 16 + (lane >> 2);
                #pragma unroll
                for (int nt = 0; nt < 4; ++nt) {
                    int cg = nh * 128 + n0 + nt * 8 + cl2;
                    int q = cg >> 6, nc = cg & 63;
                    uint32_t off  = SWZ((uint32_t)(r * 128 + nc * 2));
                    uint32_t off2 = SWZ((uint32_t)((r + 8) * 128 + nc * 2));
                    uint32_t hu, lu;
                    split2(fmaxf(C[mt][nt][0], 0.f), fmaxf(C[mt][nt][1], 0.f), hu, lu);
                    *(uint32_t*)(smch + H1HI_OFF(q) + off) = hu;
                    *(uint32_t*)(smch + H1LO_OFF(q) + off) = lu;
                    split2(fmaxf(C[mt][nt][2], 0.f), fmaxf(C[mt][nt][3], 0.f), hu, lu);
                    *(uint32_t*)(smch + H1HI_OFF(q) + off2) = hu;
                    *(uint32_t*)(smch + H1LO_OFF(q) + off2) = lu;
                }
            }
            if (s == 7) {
                // re-init C for nh=1; restage A(kc=0)
                #pragma unroll
                for (int mt = 0; mt < 2; ++mt)
                    #pragma unroll
                    for (int nt = 0; nt < 4; ++nt) {
                        int c = 128 + n0 + nt * 8 + cl2;
                        C[mt][nt][0] = b1f[c]; C[mt][nt][1] = b1f[c + 1];
                        C[mt][nt][2] = b1f[c]; C[mt][nt][3] = b1f[c + 1];
                    }
                STAGE_A(0);
            } else {
                // init C for layer2
                #pragma unroll
                for (int mt = 0; mt < 2; ++mt)
                    #pragma unroll
                    for (int nt = 0; nt < 4; ++nt) {
                        int c = n0 + nt * 8 + cl2;
                        C[mt][nt][0] = b2f[c]; C[mt][nt][1] = b2f[c + 1];
                        C[mt][nt][2] = b2f[c]; C[mt][nt][3] = b2f[c + 1];
                    }
            }
        } else if (s < 15) {
            STAGE_A((s + 1) & 7);
        }
    }

    // ---- h2 epilogue: relu -> f32 [128][129] (aliases h1 region) ----
    float* h2s = (float*)smch;
    {
        #pragma unroll
        for (int mt = 0; mt < 2; ++mt) {
            int r = m0 + mt * 16 + (lane >> 2);
            #pragma unroll
            for (int nt = 0; nt < 4; ++nt) {
                int c = n0 + nt * 8 + cl2;
                h2s[r * 129 + c]           = fmaxf(C[mt][nt][0], 0.f);
                h2s[r * 129 + c + 1]       = fmaxf(C[mt][nt][1], 0.f);
                h2s[(r + 8) * 129 + c]     = fmaxf(C[mt][nt][2], 0.f);
                h2s[(r + 8) * 129 + c + 1] = fmaxf(C[mt][nt][3], 0.f);
            }
        }
    }
    __syncthreads();

    // ---- layer 3 + tanh: 4 threads per grid row ----
    {
        const int r = tid >> 2, q4 = tid & 3;
        const float* hr = h2s + r * 129 + q4 * 32;
        const float* w3q = w3f + q4 * 32;
        float a0 = 0.f, a1 = 0.f, a2 = 0.f;
        #pragma unroll 8
        for (int k = 0; k < 32; ++k) {
            float h = hr[k];
            a0 = fmaf(h, w3q[k],       a0);
            a1 = fmaf(h, w3q[128 + k], a1);
            a2 = fmaf(h, w3q[256 + k], a2);
        }
        a0 += __shfl_xor_sync(0xffffffffu, a0, 1);
        a0 += __shfl_xor_sync(0xffffffffu, a0, 2);
        a1 += __shfl_xor_sync(0xffffffffu, a1, 1);
        a1 += __shfl_xor_sync(0xffffffffu, a1, 2);
        a2 += __shfl_xor_sync(0xffffffffu, a2, 1);
        a2 += __shfl_xor_sync(0xffffffffu, a2, 2);
        if (q4 == 0) {
            int p = tile * TG + r;
            if (p < G) {
                float* o = out + ((size_t)m * G + p) * OUTD;
                o[0] = tanhf(a0 + b3[m * OUTD + 0]);
                o[1] = tanhf(a1 + b3[m * OUTD + 1]);
                o[2] = tanhf(a2 + b3[m * OUTD + 2]);
            }
        }
    }
}

// ---------------- host launcher --------------------------------------
extern "C" void kernel_launch(void* const* d_in, const int* in_sizes, int n_in,
                              void* d_out, int out_size) {
    const float* x0  = (const float*)d_in[0];
    const float* W0a = (const float*)d_in[1];
    const float* b0a = (const float*)d_in[2];
    const float* W0b = (const float*)d_in[3];
    const float* b0b = (const float*)d_in[4];
    const float* W1  = (const float*)d_in[5];
    const float* b1  = (const float*)d_in[6];
    const float* W2  = (const float*)d_in[7];
    const float* b2  = (const float*)d_in[8];
    const float* W3  = (const float*)d_in[9];
    const float* b3  = (const float*)d_in[10];
    const int*   np  = (const int*)d_in[11];

    int G = out_size / (N_MLP * OUTD);

    prep_c0<<<(N_MLP * S0 * 32 + 255) / 256, 256>>>(x0, W0a, b0a, b0b, W0b);
    prep_split<<<1024, 256>>>(W1, W2);

    static bool attr_set = false;
    if (!attr_set) {
        cudaFuncSetAttribute(mlp_hmma, cudaFuncAttributeMaxDynamicSharedMemorySize,
                             SMEM_TOTAL);
        attr_set = true;
    }
    dim3 grid((G + TG - 1) / TG, N_MLP);
    mlp_hmma<<<grid, NTHR, SMEM_TOTAL>>>(b1, b2, W3, b3, np, (float*)d_out, G);
}

// round 6
// speedup vs baseline: 1.5309x; 1.5309x over previous
#include <cuda_runtime.h>
#include <cuda_bf16.h>
#include <math.h>
#include <stdint.h>

#define N_MLP  16
#define LATENT 1024
#define S0     512
#define S1     256
#define S2     128
#define OUTD   3
#define TG     128
#define NTHR   256

// ---------------- SMEM layout (bytes) --------------------------------
// h1 q-tiles: q*32768 (hi 16K | lo 16K), q=0..3         0      .. 131072
// A buf aliases q3 (q3 written only at s==15 epilogue, after A's last use)
// B double buffers                                      131072 .. 196608
// consts                                                196608 .. 206864
#define H1HI_OFF(q) ((q)*32768u)
#define H1LO_OFF(q) ((q)*32768u + 16384u)
#define AHI_OFF 98304u
#define ALO_OFF 114688u
#define BHI_OFF(b) (131072u + (b)*32768u)
#define BLO_OFF(b) (131072u + (b)*32768u + 16384u)
#define CONST_OFF 196608u
// const floats: c0f 0 | wxf 512 | wyf 1024 | b1f 1536 | b2f 1792 |
//               w3f 1920 | b3f 2304 | gxf 2308 | gyf 2436  -> 2564 floats
#define SMEM_TOTAL (CONST_OFF + 2564u * 4u)

#define SWZ(x) ((x) ^ (((x) >> 3) & 0x70u))

// ---------------- device scratch --------------------------------------
__device__ __align__(16) __nv_bfloat16 g_W1hi[N_MLP * S1 * S0];
__device__ __align__(16) __nv_bfloat16 g_W1lo[N_MLP * S1 * S0];
__device__ __align__(16) __nv_bfloat16 g_W2hi[N_MLP * S2 * S1];
__device__ __align__(16) __nv_bfloat16 g_W2lo[N_MLP * S2 * S1];
__device__ float g_c0[N_MLP * S0];

// ---------------- helpers ---------------------------------------------
__device__ __forceinline__ uint32_t smem_u32(const void* p) {
    uint32_t a;
    asm("{ .reg .u64 t; cvta.to.shared.u64 t, %1; cvt.u32.u64 %0, t; }"
        : "=r"(a) : "l"(p));
    return a;
}
__device__ __forceinline__ void ldsm4(uint32_t* r, uint32_t addr) {
    asm volatile("ldmatrix.sync.aligned.m8n8.x4.shared.b16 {%0,%1,%2,%3}, [%4];"
                 : "=r"(r[0]), "=r"(r[1]), "=r"(r[2]), "=r"(r[3]) : "r"(addr));
}
__device__ __forceinline__ void mma_bf16(float* d, const uint32_t* a, const uint32_t* b) {
    asm volatile(
        "mma.sync.aligned.m16n8k16.row.col.f32.bf16.bf16.f32 "
        "{%0,%1,%2,%3}, {%4,%5,%6,%7}, {%8,%9}, {%0,%1,%2,%3};"
        : "+f"(d[0]), "+f"(d[1]), "+f"(d[2]), "+f"(d[3])
        : "r"(a[0]), "r"(a[1]), "r"(a[2]), "r"(a[3]), "r"(b[0]), "r"(b[1]));
}
__device__ __forceinline__ void split2(float a, float b, uint32_t& hi, uint32_t& lo) {
    __nv_bfloat16 ha = __float2bfloat16(a), hb = __float2bfloat16(b);
    float ra = a - __bfloat162float(ha);
    float rb = b - __bfloat162float(hb);
    __nv_bfloat16 la = __float2bfloat16(ra), lb = __float2bfloat16(rb);
    hi = ((uint32_t)__bfloat16_as_ushort(hb) << 16) | (uint32_t)__bfloat16_as_ushort(ha);
    lo = ((uint32_t)__bfloat16_as_ushort(lb) << 16) | (uint32_t)__bfloat16_as_ushort(la);
}
__device__ __forceinline__ void cpa16(uint32_t dst, const void* src) {
    asm volatile("cp.async.cg.shared.global [%0], [%1], 16;"
                 :: "r"(dst), "l"(src) : "memory");
}
#define CP_COMMIT() asm volatile("cp.async.commit_group;" ::: "memory")
#define CP_WAIT1()  asm volatile("cp.async.wait_group 1;" ::: "memory")
#define CP_WAIT0()  asm volatile("cp.async.wait_group 0;" ::: "memory")

// ---------------- prep kernels ----------------------------------------
__global__ void prep_c0(const float* __restrict__ x0,
                        const float* __restrict__ W0a,
                        const float* __restrict__ b0a,
                        const float* __restrict__ b0b) {
    int w    = (blockIdx.x * blockDim.x + threadIdx.x) >> 5;
    int lane = threadIdx.x & 31;
    if (w >= N_MLP * S0) return;
    const float* row = W0a + (size_t)w * LATENT;
    float s = 0.f;
    #pragma unroll 4
    for (int i = lane; i < LATENT; i += 32) s += row[i] * x0[i];
    #pragma unroll
    for (int off = 16; off; off >>= 1) s += __shfl_xor_sync(0xffffffffu, s, off);
    if (lane == 0) g_c0[w] = s + b0a[w] + b0b[w];
}

__global__ void prep_split(const float* __restrict__ W1,
                           const float* __restrict__ W2) {
    const int t1 = N_MLP * S1 * S0;
    for (int i = blockIdx.x * blockDim.x + threadIdx.x; i < t1;
         i += gridDim.x * blockDim.x) {
        float v = W1[i];
        __nv_bfloat16 h = __float2bfloat16(v);
        g_W1hi[i] = h;
        g_W1lo[i] = __float2bfloat16(v - __bfloat162float(h));
    }
    const int t2 = N_MLP * S2 * S1;
    for (int i = blockIdx.x * blockDim.x + threadIdx.x; i < t2;
         i += gridDim.x * blockDim.x) {
        float v = W2[i];
        __nv_bfloat16 h = __float2bfloat16(v);
        g_W2hi[i] = h;
        g_W2lo[i] = __float2bfloat16(v - __bfloat162float(h));
    }
}

// ---------------- main HMMA kernel -------------------------------------
__global__ __launch_bounds__(NTHR, 1)
void mlp_hmma(const float* __restrict__ W0b,
              const float* __restrict__ b1,
              const float* __restrict__ b2,
              const float* __restrict__ W3,
              const float* __restrict__ b3,
              const int*   __restrict__ n_ptr,
              float*       __restrict__ out,
              int G) {
    extern __shared__ char smch[];
    const uint32_t smb = smem_u32(smch);
    float* c0f = (float*)(smch + CONST_OFF);
    float* wxf = c0f + 512;
    float* wyf = c0f + 1024;
    float* b1f = c0f + 1536;
    float* b2f = c0f + 1792;
    float* w3f = c0f + 1920;
    float* b3f = c0f + 2304;
    float* gxf = c0f + 2308;
    float* gyf = c0f + 2436;

    const int m    = blockIdx.y;
    const int tile = blockIdx.x;
    const int tid  = threadIdx.x;
    const int w    = tid >> 5;
    const int lane = tid & 31;
    const int n    = *n_ptr;

    // ---- stage per-MLP constants ----
    for (int i = tid; i < S0; i += NTHR) {
        c0f[i] = g_c0[m * S0 + i];
        wxf[i] = W0b[((size_t)m * S0 + i) * 2 + 0];
        wyf[i] = W0b[((size_t)m * S0 + i) * 2 + 1];
    }
    for (int i = tid; i < S1; i += NTHR) b1f[i] = b1[m * S1 + i];
    for (int i = tid; i < S2; i += NTHR) b2f[i] = b2[m * S2 + i];
    for (int i = tid; i < OUTD * S2; i += NTHR) w3f[i] = W3[(size_t)m * OUTD * S2 + i];
    if (tid < OUTD) b3f[tid] = b3[m * OUTD + tid];
    if (tid < TG) {
        int p = tile * TG + tid;
        int px = 0, py = 0;
        if (p < G) { px = p % n; py = p / n; }
        float step = 2.0f / (float)(n - 1);
        gxf[tid] = -1.0f + step * (float)px;
        gyf[tid] = -1.0f + step * (float)py;
    }
    __syncthreads();

    const int mw = w & 3, nw = w >> 2;
    const int m0 = mw * 32, n0 = nw * 64;
    const int r128 = tid & 127, half = tid >> 7;
    const float gxr = gxf[r128], gyr = gyf[r128];

    const uint32_t a_row = (uint32_t)(lane & 15);
    const uint32_t a_col = (uint32_t)((lane >> 4) * 16);
    const uint32_t b_row = (uint32_t)((lane & 7) + ((lane & 16) >> 1));
    const uint32_t b_col = (uint32_t)(((lane >> 3) & 1) * 16);
    const int cl2 = (lane & 3) * 2;

    float C[2][8][4];

    #define STAGE_A(kc) do {                                                   \
        char* ph = smch + AHI_OFF;                                             \
        char* pl = smch + ALO_OFF;                                             \
        _Pragma("unroll")                                                      \
        for (int i = 0; i < 8; ++i) {                                          \
            int kl = half * 32 + i * 4;                                        \
            int k  = (kc) * 64 + kl;                                           \
            float4 c4 = *(const float4*)(c0f + k);                             \
            float4 x4 = *(const float4*)(wxf + k);                             \
            float4 y4 = *(const float4*)(wyf + k);                             \
            float v0 = fmaxf(fmaf(x4.x, gxr, fmaf(y4.x, gyr, c4.x)), 0.f);     \
            float v1 = fmaxf(fmaf(x4.y, gxr, fmaf(y4.y, gyr, c4.y)), 0.f);     \
            float v2 = fmaxf(fmaf(x4.z, gxr, fmaf(y4.z, gyr, c4.z)), 0.f);     \
            float v3 = fmaxf(fmaf(x4.w, gxr, fmaf(y4.w, gyr, c4.w)), 0.f);     \
            uint32_t h0u, lo0u, h1u, lo1u;                                     \
            split2(v0, v1, h0u, lo0u);                                         \
            split2(v2, v3, h1u, lo1u);                                         \
            uint32_t off = SWZ((uint32_t)(r128 * 128 + kl * 2));               \
            *(uint2*)(ph + off) = make_uint2(h0u, h1u);                        \
            *(uint2*)(pl + off) = make_uint2(lo0u, lo1u);                      \
        }                                                                      \
    } while (0)

    #define ISSUE_B(s) do {                                                    \
        int bb = (s) & 1;                                                      \
        const uint4 *sh, *sl; int strd;                                        \
        if ((s) < 16) {                                                        \
            int nh = (s) >> 3, kc = (s) & 7;                                   \
            sh = (const uint4*)g_W1hi + ((size_t)m * 256 + nh * 128) * 64 + kc * 8; \
            sl = (const uint4*)g_W1lo + ((size_t)m * 256 + nh * 128) * 64 + kc * 8; \
            strd = 64;                                                         \
        } else {                                                               \
            int kc = (s) - 16;                                                 \
            sh = (const uint4*)g_W2hi + (size_t)m * 128 * 32 + kc * 8;         \
            sl = (const uint4*)g_W2lo + (size_t)m * 128 * 32 + kc * 8;         \
            strd = 32;                                                         \
        }                                                                      \
        _Pragma("unroll")                                                      \
        for (int jj = 0; jj < 4; ++jj) {                                       \
            int idx = tid + jj * NTHR;                                         \
            int row = idx >> 3, c16 = idx & 7;                                 \
            uint32_t off = SWZ((uint32_t)(row * 128 + c16 * 16));              \
            cpa16(smb + BHI_OFF(bb) + off, sh + row * strd + c16);             \
            cpa16(smb + BLO_OFF(bb) + off, sl + row * strd + c16);             \
        }                                                                      \
        CP_COMMIT();                                                           \
    } while (0)

    #define INIT_C(bias, base) do {                                            \
        _Pragma("unroll")                                                      \
        for (int mt = 0; mt < 2; ++mt)                                         \
            _Pragma("unroll")                                                  \
            for (int nt = 0; nt < 8; ++nt) {                                   \
                int c = (base) + n0 + nt * 8 + cl2;                            \
                C[mt][nt][0] = (bias)[c]; C[mt][nt][1] = (bias)[c + 1];        \
                C[mt][nt][2] = (bias)[c]; C[mt][nt][3] = (bias)[c + 1];        \
            }                                                                  \
    } while (0)

    #define H1_EPI(nh) do {                                                    \
        _Pragma("unroll")                                                      \
        for (int mt = 0; mt < 2; ++mt) {                                       \
            int r = m0 + mt * 16 + (lane >> 2);                                \
            _Pragma("unroll")                                                  \
            for (int nt = 0; nt < 8; ++nt) {                                   \
                int cg = (nh) * 128 + n0 + nt * 8 + cl2;                       \
                int q = cg >> 6, nc = cg & 63;                                 \
                uint32_t off  = SWZ((uint32_t)(r * 128 + nc * 2));             \
                uint32_t off2 = SWZ((uint32_t)((r + 8) * 128 + nc * 2));       \
                uint32_t hu, lu;                                               \
                split2(fmaxf(C[mt][nt][0], 0.f), fmaxf(C[mt][nt][1], 0.f), hu, lu); \
                *(uint32_t*)(smch + H1HI_OFF(q) + off) = hu;                   \
                *(uint32_t*)(smch + H1LO_OFF(q) + off) = lu;                   \
                split2(fmaxf(C[mt][nt][2], 0.f), fmaxf(C[mt][nt][3], 0.f), hu, lu); \
                *(uint32_t*)(smch + H1HI_OFF(q) + off2) = hu;                  \
                *(uint32_t*)(smch + H1LO_OFF(q) + off2) = lu;                  \
            }                                                                  \
        }                                                                      \
    } while (0)

    STAGE_A(0);
    ISSUE_B(0);
    ISSUE_B(1);
    INIT_C(b1f, 0);

    #pragma unroll 1
    for (int s = 0; s < 20; ++s) {
        if (s == 19) { CP_WAIT0(); } else { CP_WAIT1(); }
        __syncthreads();

        uint32_t aHIb, aLOb;
        if (s < 16) { aHIb = smb + AHI_OFF; aLOb = smb + ALO_OFF; }
        else        { int q = s - 16; aHIb = smb + H1HI_OFF(q); aLOb = smb + H1LO_OFF(q); }
        const uint32_t bHIb = smb + BHI_OFF(s & 1), bLOb = smb + BLO_OFF(s & 1);

        #pragma unroll
        for (int k16 = 0; k16 < 4; ++k16) {
            const uint32_t kb2 = (uint32_t)(k16 * 32);
            uint32_t ahi[2][4], alo[2][4], bh[4][4], bl[4][4];
            #pragma unroll
            for (int mt = 0; mt < 2; ++mt) {
                uint32_t aoff = SWZ((uint32_t)((m0 + mt * 16 + a_row) * 128) + kb2 + a_col);
                ldsm4(ahi[mt], aHIb + aoff);
                ldsm4(alo[mt], aLOb + aoff);
            }
            #pragma unroll
            for (int nt2 = 0; nt2 < 4; ++nt2) {
                uint32_t boff = SWZ((uint32_t)((n0 + nt2 * 16 + b_row) * 128) + kb2 + b_col);
                ldsm4(bh[nt2], bHIb + boff);
                ldsm4(bl[nt2], bLOb + boff);
            }
            // pass 1: ahi x bhi (16 independent MMAs)
            #pragma unroll
            for (int mt = 0; mt < 2; ++mt)
                #pragma unroll
                for (int nt2 = 0; nt2 < 4; ++nt2)
                    #pragma unroll
                    for (int s2 = 0; s2 < 2; ++s2)
                        mma_bf16(C[mt][nt2 * 2 + s2], ahi[mt], bh[nt2] + 2 * s2);
            // pass 2: ahi x blo
            #pragma unroll
            for (int mt = 0; mt < 2; ++mt)
                #pragma unroll
                for (int nt2 = 0; nt2 < 4; ++nt2)
                    #pragma unroll
                    for (int s2 = 0; s2 < 2; ++s2)
                        mma_bf16(C[mt][nt2 * 2 + s2], ahi[mt], bl[nt2] + 2 * s2);
            // pass 3: alo x bhi
            #pragma unroll
            for (int mt = 0; mt < 2; ++mt)
                #pragma unroll
                for (int nt2 = 0; nt2 < 4; ++nt2)
                    #pragma unroll
                    for (int s2 = 0; s2 < 2; ++s2)
                        mma_bf16(C[mt][nt2 * 2 + s2], alo[mt], bh[nt2] + 2 * s2);
        }
        __syncthreads();

        if (s + 2 < 20) ISSUE_B(s + 2);

        if (s == 7) {
            H1_EPI(0);
            INIT_C(b1f, 128);
            STAGE_A(0);
        } else if (s == 15) {
            H1_EPI(1);
            INIT_C(b2f, 0);
        } else if (s < 15) {
            STAGE_A((s + 1) & 7);
        }
    }

    // ---- h2 epilogue: relu -> f32 [128][129] (aliases h1 region) ----
    float* h2s = (float*)smch;
    #pragma unroll
    for (int mt = 0; mt < 2; ++mt) {
        int r = m0 + mt * 16 + (lane >> 2);
        #pragma unroll
        for (int nt = 0; nt < 8; ++nt) {
            int c = n0 + nt * 8 + cl2;
            h2s[r * 129 + c]           = fmaxf(C[mt][nt][0], 0.f);
            h2s[r * 129 + c + 1]       = fmaxf(C[mt][nt][1], 0.f);
            h2s[(r + 8) * 129 + c]     = fmaxf(C[mt][nt][2], 0.f);
            h2s[(r + 8) * 129 + c + 1] = fmaxf(C[mt][nt][3], 0.f);
        }
    }
    __syncthreads();

    // ---- layer 3 + tanh ----
    if (tid < TG) {
        const float* hr = h2s + tid * 129;
        float a0 = b3f[0], a1 = b3f[1], a2 = b3f[2];
        #pragma unroll 8
        for (int k = 0; k < S2; ++k) {
            float h = hr[k];
            a0 = fmaf(h, w3f[k],        a0);
            a1 = fmaf(h, w3f[128 + k],  a1);
            a2 = fmaf(h, w3f[256 + k],  a2);
        }
        int p = tile * TG + tid;
        if (p < G) {
            float* o = out + ((size_t)m * G + p) * OUTD;
            o[0] = tanhf(a0);
            o[1] = tanhf(a1);
            o[2] = tanhf(a2);
        }
    }
}

// ---------------- host launcher ----------------------------------------
extern "C" void kernel_launch(void* const* d_in, const int* in_sizes, int n_in,
                              void* d_out, int out_size) {
    const float* x0  = (const float*)d_in[0];
    const float* W0a = (const float*)d_in[1];
    const float* b0a = (const float*)d_in[2];
    const float* W0b = (const float*)d_in[3];
    const float* b0b = (const float*)d_in[4];
    const float* W1  = (const float*)d_in[5];
    const float* b1  = (const float*)d_in[6];
    const float* W2  = (const float*)d_in[7];
    const float* b2  = (const float*)d_in[8];
    const float* W3  = (const float*)d_in[9];
    const float* b3  = (const float*)d_in[10];
    const int*   np  = (const int*)d_in[11];

    int G = out_size / (N_MLP * OUTD);

    prep_c0<<<(N_MLP * S0 * 32 + 255) / 256, 256>>>(x0, W0a, b0a, b0b);
    prep_split<<<1024, 256>>>(W1, W2);

    static bool attr_set = false;
    if (!attr_set) {
        cudaFuncSetAttribute(mlp_hmma, cudaFuncAttributeMaxDynamicSharedMemorySize,
                             SMEM_TOTAL);
        attr_set = true;
    }
    dim3 grid((G + TG - 1) / TG, N_MLP);
    mlp_hmma<<<grid, NTHR, SMEM_TOTAL>>>(W0b, b1, b2, W3, b3, np, (float*)d_out, G);
}